// round 3
// baseline (speedup 1.0000x reference)
#include <cuda_runtime.h>
#include <cuda_bf16.h>
#include <math.h>

// Shapes: B=256, D=512, L=64, H=300
// Flattened decoder rows: BD = 131072, CTA tile = 128 rows (same b per CTA).
// Padded dims: K(h) padded to 320, N(g) padded to 384 for guard-free loops.

#define Bc 256
#define Dc 512
#define Lc 64
#define Hc 300
#define HP 320         // padded K for stage B (g1 columns)
#define NPAD 384       // padded g/n dimension
#define BD (Bc*Dc)

// ---------------- device scratch (no allocations allowed) ----------------
__device__ float g_g1T[64 * NPAD];        // [l][h]  = gen1_w[h][l], h<300 else 0
__device__ float g_g2T[HP * NPAD];        // [h][g]  = gen2_w[g][h], valid<300 else 0
__device__ float g_headp[Dc * NPAD];      // [d][g]  = head_w[d][g], g<300 else 0
__device__ float g_biasp[NPAD];           // gen2_b padded
__device__ float g_h1[Bc * Hc];
__device__ float g_h2[Bc * Hc];

// ---------------- packed fp32x2 FMA (B300 full-rate fp32 path) ----------------
union F2U { float2 f; unsigned long long u; };
__device__ __forceinline__ float2 ffma2(float2 a, float2 b, float2 c) {
    F2U A, Bv, Cv; A.f = a; Bv.f = b; Cv.f = c;
    asm("fma.rn.f32x2 %0, %1, %2, %0;" : "+l"(Cv.u) : "l"(A.u), "l"(Bv.u));
    return Cv.f;
}

// ---------------- prep: pad + transpose weights ----------------
__global__ void prep_kernel(const float* __restrict__ g1w,
                            const float* __restrict__ g2w,
                            const float* __restrict__ hw,
                            const float* __restrict__ g2b) {
    const int n1 = 64 * NPAD;
    const int n2 = n1 + HP * NPAD;
    const int n3 = n2 + Dc * NPAD;
    const int n4 = n3 + NPAD;
    int i = blockIdx.x * blockDim.x + threadIdx.x;
    if (i >= n4) return;
    if (i < n1) {
        int l = i / NPAD, h = i % NPAD;
        g_g1T[i] = (h < Hc) ? g1w[h * Lc + l] : 0.f;
    } else if (i < n2) {
        int j = i - n1; int h = j / NPAD, g = j % NPAD;
        g_g2T[j] = (h < Hc && g < Hc) ? g2w[g * Hc + h] : 0.f;
    } else if (i < n3) {
        int j = i - n2; int d = j / NPAD, g = j % NPAD;
        g_headp[j] = (g < Hc) ? hw[d * Hc + g] : 0.f;
    } else {
        int g = i - n3;
        g_biasp[g] = (g < Hc) ? g2b[g] : 0.f;
    }
}

// ---------------- small generic GEMM for the encoder ----------------
// C[m][n] = act(bias[n] + sum_k A[m][k]*Bw[n][k])
__global__ void gemm_kernel(const float* __restrict__ A, int lda,
                            const float* __restrict__ Bw, int ldb,
                            const float* __restrict__ bias,
                            float* __restrict__ C, int ldc,
                            int M, int N, int K, int relu) {
    __shared__ float As[32][33];
    __shared__ float Bs[32][33];
    int tx = threadIdx.x, ty = threadIdx.y;
    int bm = blockIdx.y * 32, bn = blockIdx.x * 32;
    float acc00 = 0.f, acc01 = 0.f, acc10 = 0.f, acc11 = 0.f;
    int t = ty * 16 + tx;
    for (int k0 = 0; k0 < K; k0 += 32) {
        for (int i = t; i < 32 * 32; i += 256) {
            int r = i >> 5, c = i & 31;
            int gm = bm + r, gk = k0 + c, gn = bn + r;
            As[r][c] = (gm < M && gk < K) ? A[gm * lda + gk] : 0.f;
            Bs[r][c] = (gn < N && gk < K) ? Bw[gn * ldb + gk] : 0.f;
        }
        __syncthreads();
#pragma unroll 8
        for (int kk = 0; kk < 32; kk++) {
            float a0 = As[ty * 2][kk], a1 = As[ty * 2 + 1][kk];
            float b0 = Bs[tx * 2][kk], b1 = Bs[tx * 2 + 1][kk];
            acc00 += a0 * b0; acc01 += a0 * b1;
            acc10 += a1 * b0; acc11 += a1 * b1;
        }
        __syncthreads();
    }
#pragma unroll
    for (int i = 0; i < 2; i++) {
#pragma unroll
        for (int j = 0; j < 2; j++) {
            int m = bm + ty * 2 + i, n = bn + tx * 2 + j;
            if (m < M && n < N) {
                float v = (i == 0 ? (j == 0 ? acc00 : acc01) : (j == 0 ? acc10 : acc11)) + bias[n];
                if (relu) v = fmaxf(v, 0.f);
                C[m * ldc + n] = v;
            }
        }
    }
}

// ---------------- z = z_mean + eps * exp(0.5*z_log_var) ----------------
__global__ void z_kernel(const float* __restrict__ zm, const float* __restrict__ zlv,
                         const float* __restrict__ eps, float* __restrict__ z, int n) {
    int i = blockIdx.x * blockDim.x + threadIdx.x;
    if (i < n) z[i] = zm[i] + eps[i] * expf(0.5f * zlv[i]);
}

// ---------------- fused decoder ----------------
// grid = 1024 CTAs, each owns 128 rows (one b, d in [d0, d0+128)).
// smem: g1s[320][128] (160KB) | msf[64][128] (32KB, reused as partial) | wtb 2x[32][128] (32KB)
__global__ __launch_bounds__(256, 1)
void decoder_kernel(const float* __restrict__ W,
                    const float* __restrict__ z_all,
                    const float* __restrict__ head_b,
                    float* __restrict__ xmean) {
    extern __shared__ float sm[];
    float* g1s = sm;                  // 40960 floats
    float* msf = sm + 40960;          // 8192 floats (masked, later partial sums)
    float* wtb = sm + 40960 + 8192;   // 8192 floats (stage-A weights / stage-B dbuf)

    const int tid = threadIdx.x;
    const int tx = tid & 15;
    const int ty = tid >> 4;
    const int r0 = blockIdx.x * 128;
    const int b = r0 >> 9;
    const int d0 = r0 & 511;
    const float* zrow = z_all + b * Lc;

    // ---- masked[l][m] = z[b][l] * W[d0+m][l]  (transposed into smem) ----
    for (int t = tid; t < 2048; t += 256) {
        int m = t >> 4;
        int l4 = t & 15;
        float4 w4 = *(const float4*)&W[(d0 + m) * Lc + l4 * 4];
        float4 z4 = *(const float4*)&zrow[l4 * 4];
        int base = (l4 * 4) * 128 + m;
        msf[base]       = w4.x * z4.x;
        msf[base + 128] = w4.y * z4.y;
        msf[base + 256] = w4.z * z4.z;
        msf[base + 384] = w4.w * z4.w;
    }
    __syncthreads();

    // ---- stage A: g1s[h][m] = relu(sum_l masked[l][m] * gen1_w[h][l]) ----
    for (int p = 0; p < 3; p++) {
        int h0 = p * 128;
        for (int f = tid; f < 2048; f += 256) {   // load gen1T chunk [64l x 128h]
            int l = f >> 5;
            int h4 = f & 31;
            *(float4*)&wtb[l * 128 + h4 * 4] = *(const float4*)&g_g1T[l * NPAD + h0 + h4 * 4];
        }
        __syncthreads();

        float2 c[8][4];
#pragma unroll
        for (int i = 0; i < 8; i++)
#pragma unroll
            for (int j = 0; j < 4; j++) c[i][j] = make_float2(0.f, 0.f);

#pragma unroll 8
        for (int l = 0; l < 64; l++) {
            float4 a0 = *(const float4*)&msf[l * 128 + tx * 4];
            float4 a1 = *(const float4*)&msf[l * 128 + 64 + tx * 4];
            float2 ap[4] = {{a0.x, a0.y}, {a0.z, a0.w}, {a1.x, a1.y}, {a1.z, a1.w}};
            float4 b0 = *(const float4*)&wtb[l * 128 + ty * 4];
            float4 b1 = *(const float4*)&wtb[l * 128 + 64 + ty * 4];
            float bb[8] = {b0.x, b0.y, b0.z, b0.w, b1.x, b1.y, b1.z, b1.w};
#pragma unroll
            for (int h = 0; h < 8; h++) {
                float2 bd = make_float2(bb[h], bb[h]);
#pragma unroll
                for (int mp = 0; mp < 4; mp++) c[h][mp] = ffma2(ap[mp], bd, c[h][mp]);
            }
        }
        // relu + store (rows h>=320 dropped)
#pragma unroll
        for (int h = 0; h < 8; h++) {
            int hl = (h < 4) ? (ty * 4 + h) : (64 + ty * 4 + (h - 4));
            int hg = h0 + hl;
            if (hg < HP) {
                float4 v0, v1;
                v0.x = fmaxf(c[h][0].x, 0.f); v0.y = fmaxf(c[h][0].y, 0.f);
                v0.z = fmaxf(c[h][1].x, 0.f); v0.w = fmaxf(c[h][1].y, 0.f);
                v1.x = fmaxf(c[h][2].x, 0.f); v1.y = fmaxf(c[h][2].y, 0.f);
                v1.z = fmaxf(c[h][3].x, 0.f); v1.w = fmaxf(c[h][3].y, 0.f);
                *(float4*)&g1s[hg * 128 + tx * 4] = v0;
                *(float4*)&g1s[hg * 128 + 64 + tx * 4] = v1;
            }
        }
        __syncthreads();
    }

    // ---- zero partial sums (reuse msf region: partial[m][tx16]) ----
    for (int t = tid; t < 2048; t += 256) msf[t] = 0.f;
    __syncthreads();

    // ---- stage B: g2 + head contraction, fused, K=320, 3 n-passes of 128 ----
    float4 pre[4];
    for (int p = 0; p < 3; p++) {
        int g0 = p * 128;
        float2 c[8][4];
#pragma unroll
        for (int i = 0; i < 8; i++)
#pragma unroll
            for (int j = 0; j < 4; j++) c[i][j] = make_float2(0.f, 0.f);

        // prologue: chunk 0 -> buf0
#pragma unroll
        for (int j = 0; j < 4; j++) {
            int f = tid + j * 256; int k = f >> 5; int n4 = f & 31;
            pre[j] = *(const float4*)&g_g2T[k * NPAD + g0 + n4 * 4];
        }
#pragma unroll
        for (int j = 0; j < 4; j++) {
            int f = tid + j * 256; int k = f >> 5; int n4 = f & 31;
            *(float4*)&wtb[k * 128 + n4 * 4] = pre[j];
        }
        __syncthreads();

        for (int kc = 0; kc < 10; kc++) {
            const float* wb = wtb + (kc & 1) * 4096;
            if (kc < 9) {
                int k0n = (kc + 1) * 32;
#pragma unroll
                for (int j = 0; j < 4; j++) {
                    int f = tid + j * 256; int k = f >> 5; int n4 = f & 31;
                    pre[j] = *(const float4*)&g_g2T[(k0n + k) * NPAD + g0 + n4 * 4];
                }
            }
            int kb = kc * 32;
#pragma unroll 8
            for (int k = 0; k < 32; k++) {
                const float* g1r = &g1s[(kb + k) * 128];
                float4 a0 = *(const float4*)&g1r[ty * 4];
                float4 a1 = *(const float4*)&g1r[64 + ty * 4];
                float aa[8] = {a0.x, a0.y, a0.z, a0.w, a1.x, a1.y, a1.z, a1.w};
                float4 b0 = *(const float4*)&wb[k * 128 + tx * 4];
                float4 b1 = *(const float4*)&wb[k * 128 + 64 + tx * 4];
                float2 bp[4] = {{b0.x, b0.y}, {b0.z, b0.w}, {b1.x, b1.y}, {b1.z, b1.w}};
#pragma unroll
                for (int m = 0; m < 8; m++) {
                    float2 ad = make_float2(aa[m], aa[m]);
#pragma unroll
                    for (int np = 0; np < 4; np++) c[m][np] = ffma2(ad, bp[np], c[m][np]);
                }
            }
            if (kc < 9) {
                float* wo = wtb + ((kc + 1) & 1) * 4096;
#pragma unroll
                for (int j = 0; j < 4; j++) {
                    int f = tid + j * 256; int k = f >> 5; int n4 = f & 31;
                    *(float4*)&wo[k * 128 + n4 * 4] = pre[j];
                }
            }
            __syncthreads();
        }

        // epilogue: relu(bias+acc) dotted with head_w row; accumulate per-thread partials
#pragma unroll
        for (int m = 0; m < 8; m++) {
            int ml = (m < 4) ? (ty * 4 + m) : (64 + ty * 4 + (m - 4));
            int d = d0 + ml;
            const float* hrow = &g_headp[d * NPAD + g0];
            float s = 0.f;
#pragma unroll
            for (int np = 0; np < 4; np++) {
                int nl = (np < 2) ? (tx * 4 + 2 * np) : (64 + tx * 4 + 2 * (np - 2));
                float2 b2 = *(const float2*)&g_biasp[g0 + nl];
                float2 h2 = *(const float2*)&hrow[nl];
                float gx = fmaxf(c[m][np].x + b2.x, 0.f);
                float gy = fmaxf(c[m][np].y + b2.y, 0.f);
                s += gx * h2.x + gy * h2.y;
            }
            msf[ml * 16 + tx] += s;   // owner-thread RMW, no race
        }
    }
    __syncthreads();

    if (tid < 128) {
        float s = head_b[d0 + tid];
#pragma unroll
        for (int t = 0; t < 16; t++) s += msf[tid * 16 + t];
        xmean[r0 + tid] = s;
    }
}

// ---------------- launch ----------------
extern "C" void kernel_launch(void* const* d_in, const int* in_sizes, int n_in,
                              void* d_out, int out_size) {
    const float* x      = (const float*)d_in[0];
    const float* eps    = (const float*)d_in[1];
    const float* W      = (const float*)d_in[2];
    const float* enc1_w = (const float*)d_in[3];
    const float* enc1_b = (const float*)d_in[4];
    const float* enc2_w = (const float*)d_in[5];
    const float* enc2_b = (const float*)d_in[6];
    const float* zm_w   = (const float*)d_in[7];
    const float* zm_b   = (const float*)d_in[8];
    const float* zv_w   = (const float*)d_in[9];
    const float* zv_b   = (const float*)d_in[10];
    const float* gen1_w = (const float*)d_in[11];
    const float* gen2_w = (const float*)d_in[12];
    const float* gen2_b = (const float*)d_in[13];
    const float* head_w = (const float*)d_in[14];
    const float* head_b = (const float*)d_in[15];

    float* out   = (float*)d_out;
    float* xmean = out;                    // [256*512]
    float* z     = out + BD;               // [256*64]
    float* zm    = out + BD + Bc * Lc;     // [256*64]
    float* zlv   = out + BD + 2 * Bc * Lc; // [256*64]

    // weight prep (pad + transpose)
    {
        int tot = 64 * NPAD + HP * NPAD + Dc * NPAD + NPAD;
        prep_kernel<<<(tot + 255) / 256, 256>>>(gen1_w, gen2_w, head_w, gen2_b);
    }

    // encoder
    dim3 blk(16, 16);
    gemm_kernel<<<dim3((Hc + 31) / 32, (Bc + 31) / 32), blk>>>(
        x, Dc, enc1_w, Dc, enc1_b, g_h1, Hc, Bc, Hc, Dc, 1);
    gemm_kernel<<<dim3((Hc + 31) / 32, (Bc + 31) / 32), blk>>>(
        g_h1, Hc, enc2_w, Hc, enc2_b, g_h2, Hc, Bc, Hc, Hc, 1);
    gemm_kernel<<<dim3((Lc + 31) / 32, (Bc + 31) / 32), blk>>>(
        g_h2, Hc, zm_w, Hc, zm_b, zm, Lc, Bc, Lc, Hc, 0);
    gemm_kernel<<<dim3((Lc + 31) / 32, (Bc + 31) / 32), blk>>>(
        g_h2, Hc, zv_w, Hc, zv_b, zlv, Lc, Bc, Lc, Hc, 0);
    z_kernel<<<(Bc * Lc + 255) / 256, 256>>>(zm, zlv, eps, z, Bc * Lc);

    // fused decoder
    const int smem_bytes = (40960 + 8192 + 8192) * 4;  // 229376 B
    cudaFuncSetAttribute(decoder_kernel, cudaFuncAttributeMaxDynamicSharedMemorySize,
                         smem_bytes);
    decoder_kernel<<<BD / 128, 256, smem_bytes>>>(W, z, head_b, xmean);
}

// round 5
// speedup vs baseline: 1.2567x; 1.2567x over previous
#include <cuda_runtime.h>
#include <cuda_bf16.h>
#include <math.h>

// Shapes: B=256, D=512, L=64, H=300
#define Bc 256
#define Dc 512
#define Lc 64
#define Hc 300
#define HP 320         // padded K for stage B (g1 rows)
#define NPAD 384       // padded column stride for decoder weight scratch
#define BD (Bc*Dc)

// ---------------- device scratch (no allocations allowed) ----------------
__device__ float g_g1T[64 * NPAD];        // [l][h]  = gen1_w[h][l], h<300 else 0
__device__ float g_g2T[HP * NPAD];        // [h][g]  = gen2_w[g][h], valid<300 else 0
__device__ float g_headp[Dc * NPAD];      // [d][g]  = head_w[d][g], g<300 else 0
__device__ float g_biasp[NPAD];           // gen2_b padded
__device__ float g_e1T[512 * 320];        // [k][j]  = enc1_w[j][k], j<300 else 0
__device__ float g_e2T[320 * 320];        // [k][j]  = enc2_w[j][k], pad 0
__device__ float g_zT[320 * 128];         // [k][j]  j<64: zm_w[j][k], else zv_w[j-64][k]

// ---------------- packed fp32x2 FMA (B300 full-rate fp32 path) ----------------
union F2U { float2 f; unsigned long long u; };
__device__ __forceinline__ float2 ffma2(float2 a, float2 b, float2 c) {
    F2U A, Bv, Cv; A.f = a; Bv.f = b; Cv.f = c;
    asm("fma.rn.f32x2 %0, %1, %2, %0;" : "+l"(Cv.u) : "l"(A.u), "l"(Bv.u));
    return Cv.f;
}

// ---------------- prep: pad + transpose all weights ----------------
__global__ void prep_kernel(const float* __restrict__ g1w,
                            const float* __restrict__ g2w,
                            const float* __restrict__ hw,
                            const float* __restrict__ g2b,
                            const float* __restrict__ e1w,
                            const float* __restrict__ e2w,
                            const float* __restrict__ zmw,
                            const float* __restrict__ zvw) {
    const int n1 = 64 * NPAD;
    const int n2 = n1 + HP * NPAD;
    const int n3 = n2 + Dc * NPAD;
    const int n4 = n3 + NPAD;
    const int n5 = n4 + 512 * 320;
    const int n6 = n5 + 320 * 320;
    const int n7 = n6 + 320 * 128;
    int i = blockIdx.x * blockDim.x + threadIdx.x;
    if (i >= n7) return;
    if (i < n1) {
        int l = i / NPAD, h = i % NPAD;
        g_g1T[i] = (h < Hc) ? g1w[h * Lc + l] : 0.f;
    } else if (i < n2) {
        int j = i - n1; int h = j / NPAD, g = j % NPAD;
        g_g2T[j] = (h < Hc && g < Hc) ? g2w[g * Hc + h] : 0.f;
    } else if (i < n3) {
        int j = i - n2; int d = j / NPAD, g = j % NPAD;
        g_headp[j] = (g < Hc) ? hw[d * Hc + g] : 0.f;
    } else if (i < n4) {
        int g = i - n3;
        g_biasp[g] = (g < Hc) ? g2b[g] : 0.f;
    } else if (i < n5) {
        int j = i - n4; int k = j / 320, c = j % 320;
        g_e1T[j] = (c < Hc) ? e1w[c * Dc + k] : 0.f;
    } else if (i < n6) {
        int j = i - n5; int k = j / 320, c = j % 320;
        g_e2T[j] = (c < Hc && k < Hc) ? e2w[c * Hc + k] : 0.f;
    } else {
        int j = i - n6; int k = j / 128, c = j % 128;
        float v = 0.f;
        if (k < Hc) v = (c < 64) ? zmw[c * Hc + k] : zvw[(c - 64) * Hc + k];
        g_zT[j] = v;
    }
}

// ---------------- fused encoder: 4 batch rows per CTA, 320 threads ----------------
#define RPC 4
__global__ __launch_bounds__(320)
void enc_kernel(const float* __restrict__ x, const float* __restrict__ eps,
                const float* __restrict__ e1b, const float* __restrict__ e2b,
                const float* __restrict__ zmb, const float* __restrict__ zvb,
                float* __restrict__ zm, float* __restrict__ zlv,
                float* __restrict__ z) {
    __shared__ float xs[RPC][512];
    __shared__ float h1s[RPC][320];
    __shared__ float h2s[RPC][320];
    __shared__ float zs[RPC][128];
    const int tid = threadIdx.x;
    const int b0 = blockIdx.x * RPC;

    for (int t = tid; t < RPC * 512; t += 320)
        xs[t >> 9][t & 511] = x[(b0 + (t >> 9)) * 512 + (t & 511)];
    __syncthreads();

    const int j = tid;   // 0..319
    {   // stage 1: h1 = relu(x @ e1T + b)
        float bj = (j < Hc) ? e1b[j] : 0.f;
        float acc[RPC];
#pragma unroll
        for (int r = 0; r < RPC; r++) acc[r] = bj;
#pragma unroll 8
        for (int k = 0; k < 512; k++) {
            float w = g_e1T[k * 320 + j];
#pragma unroll
            for (int r = 0; r < RPC; r++) acc[r] += xs[r][k] * w;
        }
#pragma unroll
        for (int r = 0; r < RPC; r++) h1s[r][j] = fmaxf(acc[r], 0.f);
    }
    __syncthreads();
    {   // stage 2: h2 = relu(h1 @ e2T + b)
        float bj = (j < Hc) ? e2b[j] : 0.f;
        float acc[RPC];
#pragma unroll
        for (int r = 0; r < RPC; r++) acc[r] = bj;
#pragma unroll 8
        for (int k = 0; k < 320; k++) {
            float w = g_e2T[k * 320 + j];
#pragma unroll
            for (int r = 0; r < RPC; r++) acc[r] += h1s[r][k] * w;
        }
#pragma unroll
        for (int r = 0; r < RPC; r++) h2s[r][j] = fmaxf(acc[r], 0.f);
    }
    __syncthreads();
    if (j < 128) {   // zm | zlv projection
        float bj = (j < 64) ? zmb[j] : zvb[j - 64];
        float acc[RPC];
#pragma unroll
        for (int r = 0; r < RPC; r++) acc[r] = bj;
#pragma unroll 8
        for (int k = 0; k < 320; k++) {
            float w = g_zT[k * 128 + j];
#pragma unroll
            for (int r = 0; r < RPC; r++) acc[r] += h2s[r][k] * w;
        }
#pragma unroll
        for (int r = 0; r < RPC; r++) zs[r][j] = acc[r];
    }
    __syncthreads();
    if (j < 64) {
#pragma unroll
        for (int r = 0; r < RPC; r++) {
            int b = b0 + r;
            float m = zs[r][j], lv = zs[r][j + 64];
            zm[b * 64 + j]  = m;
            zlv[b * 64 + j] = lv;
            z[b * 64 + j]   = m + eps[b * 64 + j] * expf(0.5f * lv);
        }
    }
}

// ---------------- decoder pass helpers ----------------
// Stage A: g1s[h][m] = relu(sum_l masked[l][m] * gen1_w[h][l]), HT*16 h-cols
template<int HT>
__device__ __forceinline__ void stageA_pass(const int h0, const int tx, const int ty,
                                            const int tid,
                                            const float* __restrict__ msf,
                                            float* __restrict__ wtb,
                                            float* __restrict__ g1s) {
    constexpr int Q = HT * 4;   // float4 per l-row (HT*16 cols / 4)
    for (int f = tid; f < 64 * Q; f += 256) {
        int l = f / Q;
        int h4 = f % Q;
        *(float4*)&wtb[l * 128 + h4 * 4] = *(const float4*)&g_g1T[l * NPAD + h0 + h4 * 4];
    }
    __syncthreads();

    float2 c[HT][4];
#pragma unroll
    for (int i = 0; i < HT; i++)
#pragma unroll
        for (int jj = 0; jj < 4; jj++) c[i][jj] = make_float2(0.f, 0.f);

#pragma unroll 8
    for (int l = 0; l < 64; l++) {
        float4 a0 = *(const float4*)&msf[l * 128 + tx * 4];
        float4 a1 = *(const float4*)&msf[l * 128 + 64 + tx * 4];
        float2 ap[4] = {{a0.x, a0.y}, {a0.z, a0.w}, {a1.x, a1.y}, {a1.z, a1.w}};
        float bb[HT];
        float4 b0 = *(const float4*)&wtb[l * 128 + ty * 4];
        bb[0] = b0.x; bb[1] = b0.y; bb[2] = b0.z; bb[3] = b0.w;
        if constexpr (HT == 8) {
            float4 b1 = *(const float4*)&wtb[l * 128 + 64 + ty * 4];
            bb[4] = b1.x; bb[5] = b1.y; bb[6] = b1.z; bb[7] = b1.w;
        }
#pragma unroll
        for (int h = 0; h < HT; h++) {
            float2 bd = make_float2(bb[h], bb[h]);
#pragma unroll
            for (int mp = 0; mp < 4; mp++) c[h][mp] = ffma2(ap[mp], bd, c[h][mp]);
        }
    }
#pragma unroll
    for (int h = 0; h < HT; h++) {
        int hl = (h < 4) ? (ty * 4 + h) : (64 + ty * 4 + (h - 4));
        int hg = h0 + hl;
        float4 v0, v1;
        v0.x = fmaxf(c[h][0].x, 0.f); v0.y = fmaxf(c[h][0].y, 0.f);
        v0.z = fmaxf(c[h][1].x, 0.f); v0.w = fmaxf(c[h][1].y, 0.f);
        v1.x = fmaxf(c[h][2].x, 0.f); v1.y = fmaxf(c[h][2].y, 0.f);
        v1.z = fmaxf(c[h][3].x, 0.f); v1.w = fmaxf(c[h][3].y, 0.f);
        *(float4*)&g1s[hg * 128 + tx * 4] = v0;
        *(float4*)&g1s[hg * 128 + 64 + tx * 4] = v1;
    }
    __syncthreads();
}

// Stage B: g2 + head contraction for NT*32 n-cols starting at g0
template<int NT>
__device__ __forceinline__ void stageB_pass(const int g0, const int tx, const int ty,
                                            const int tid, const int d0,
                                            const float* __restrict__ g1s,
                                            float* __restrict__ wtb,
                                            float* __restrict__ partial) {
    constexpr int Q = NT * 8;   // float4 per k-row (NT*32 cols / 4)  [R4 fix: was NT*4]
    float2 c[8][NT];
#pragma unroll
    for (int i = 0; i < 8; i++)
#pragma unroll
        for (int jj = 0; jj < NT; jj++) c[i][jj] = make_float2(0.f, 0.f);

    float4 pre[NT];
    // prologue: chunk 0 -> buf0
#pragma unroll
    for (int jj = 0; jj < NT; jj++) {
        int f = tid + jj * 256; int k = f / Q; int n4 = f % Q;
        pre[jj] = *(const float4*)&g_g2T[k * NPAD + g0 + n4 * 4];
    }
#pragma unroll
    for (int jj = 0; jj < NT; jj++) {
        int f = tid + jj * 256; int k = f / Q; int n4 = f % Q;
        *(float4*)&wtb[k * 128 + n4 * 4] = pre[jj];
    }
    __syncthreads();

    for (int kc = 0; kc < 10; kc++) {
        const float* wb = wtb + (kc & 1) * 4096;
        if (kc < 9) {
            int k0n = (kc + 1) * 32;
#pragma unroll
            for (int jj = 0; jj < NT; jj++) {
                int f = tid + jj * 256; int k = f / Q; int n4 = f % Q;
                pre[jj] = *(const float4*)&g_g2T[(k0n + k) * NPAD + g0 + n4 * 4];
            }
        }
        int kb = kc * 32;
#pragma unroll 8
        for (int k = 0; k < 32; k++) {
            const float* g1r = &g1s[(kb + k) * 128];
            float4 a0 = *(const float4*)&g1r[ty * 4];
            float4 a1 = *(const float4*)&g1r[64 + ty * 4];
            float aa[8] = {a0.x, a0.y, a0.z, a0.w, a1.x, a1.y, a1.z, a1.w};
            float2 bp[NT];
            float4 b0 = *(const float4*)&wb[k * 128 + tx * 4];
            bp[0] = make_float2(b0.x, b0.y); bp[1] = make_float2(b0.z, b0.w);
            if constexpr (NT == 4) {
                float4 b1 = *(const float4*)&wb[k * 128 + 64 + tx * 4];
                bp[2] = make_float2(b1.x, b1.y); bp[3] = make_float2(b1.z, b1.w);
            }
#pragma unroll
            for (int m = 0; m < 8; m++) {
                float2 ad = make_float2(aa[m], aa[m]);
#pragma unroll
                for (int np = 0; np < NT; np++) c[m][np] = ffma2(ad, bp[np], c[m][np]);
            }
        }
        if (kc < 9) {
            float* wo = wtb + ((kc + 1) & 1) * 4096;
#pragma unroll
            for (int jj = 0; jj < NT; jj++) {
                int f = tid + jj * 256; int k = f / Q; int n4 = f % Q;
                *(float4*)&wo[k * 128 + n4 * 4] = pre[jj];
            }
        }
        __syncthreads();
    }

    // epilogue: relu(bias+acc) dotted with head_w row; owner-thread partials
#pragma unroll
    for (int m = 0; m < 8; m++) {
        int ml = (m < 4) ? (ty * 4 + m) : (64 + ty * 4 + (m - 4));
        int d = d0 + ml;
        const float* hrow = &g_headp[d * NPAD + g0];
        float s = 0.f;
#pragma unroll
        for (int np = 0; np < NT; np++) {
            int nl = (np < 2) ? (tx * 4 + 2 * np) : (64 + tx * 4 + 2 * (np - 2));
            float2 b2 = *(const float2*)&g_biasp[g0 + nl];
            float2 h2 = *(const float2*)&hrow[nl];
            float gx = fmaxf(c[m][np].x + b2.x, 0.f);
            float gy = fmaxf(c[m][np].y + b2.y, 0.f);
            s += gx * h2.x + gy * h2.y;
        }
        partial[ml * 16 + tx] += s;
    }
}

// ---------------- fused decoder ----------------
// grid = 1024 CTAs, each owns 128 rows (one b, d in [d0, d0+128)).
__global__ __launch_bounds__(256, 1)
void decoder_kernel(const float* __restrict__ W,
                    const float* __restrict__ z_all,
                    const float* __restrict__ head_b,
                    float* __restrict__ xmean) {
    extern __shared__ float sm[];
    float* g1s = sm;                  // 40960 floats (320 x 128)
    float* msf = sm + 40960;          // 8192 floats (masked, later partials)
    float* wtb = sm + 40960 + 8192;   // 8192 floats (weights, dbuf)

    const int tid = threadIdx.x;
    const int tx = tid & 15;
    const int ty = tid >> 4;
    const int r0 = blockIdx.x * 128;
    const int b = r0 >> 9;
    const int d0 = r0 & 511;
    const float* zrow = z_all + b * Lc;

    // masked[l][m] = z[b][l] * W[d0+m][l]  (transposed into smem)
    for (int t = tid; t < 2048; t += 256) {
        int m = t >> 4;
        int l4 = t & 15;
        float4 w4 = *(const float4*)&W[(d0 + m) * Lc + l4 * 4];
        float4 z4 = *(const float4*)&zrow[l4 * 4];
        int base = (l4 * 4) * 128 + m;
        msf[base]       = w4.x * z4.x;
        msf[base + 128] = w4.y * z4.y;
        msf[base + 256] = w4.z * z4.z;
        msf[base + 384] = w4.w * z4.w;
    }
    __syncthreads();

    // stage A: 128 + 128 + 64 h-columns = 320 rows of g1s
    stageA_pass<8>(0,   tx, ty, tid, msf, wtb, g1s);
    stageA_pass<8>(128, tx, ty, tid, msf, wtb, g1s);
    stageA_pass<4>(256, tx, ty, tid, msf, wtb, g1s);

    // zero partial sums (reuse msf region)
    for (int t = tid; t < 2048; t += 256) msf[t] = 0.f;
    __syncthreads();

    // stage B: 128 + 128 + 64 n-columns = 320 (covers N=300)
    stageB_pass<4>(0,   tx, ty, tid, d0, g1s, wtb, msf);
    stageB_pass<4>(128, tx, ty, tid, d0, g1s, wtb, msf);
    stageB_pass<2>(256, tx, ty, tid, d0, g1s, wtb, msf);
    __syncthreads();

    if (tid < 128) {
        float s = head_b[d0 + tid];
#pragma unroll
        for (int t = 0; t < 16; t++) s += msf[tid * 16 + t];
        xmean[r0 + tid] = s;
    }
}

// ---------------- launch ----------------
extern "C" void kernel_launch(void* const* d_in, const int* in_sizes, int n_in,
                              void* d_out, int out_size) {
    const float* x      = (const float*)d_in[0];
    const float* eps    = (const float*)d_in[1];
    const float* W      = (const float*)d_in[2];
    const float* enc1_w = (const float*)d_in[3];
    const float* enc1_b = (const float*)d_in[4];
    const float* enc2_w = (const float*)d_in[5];
    const float* enc2_b = (const float*)d_in[6];
    const float* zm_w   = (const float*)d_in[7];
    const float* zm_b   = (const float*)d_in[8];
    const float* zv_w   = (const float*)d_in[9];
    const float* zv_b   = (const float*)d_in[10];
    const float* gen1_w = (const float*)d_in[11];
    const float* gen2_w = (const float*)d_in[12];
    const float* gen2_b = (const float*)d_in[13];
    const float* head_w = (const float*)d_in[14];
    const float* head_b = (const float*)d_in[15];

    float* out   = (float*)d_out;
    float* xmean = out;                    // [256*512]
    float* z     = out + BD;               // [256*64]
    float* zm    = out + BD + Bc * Lc;     // [256*64]
    float* zlv   = out + BD + 2 * Bc * Lc; // [256*64]

    // weight prep (pad + transpose everything)
    {
        int tot = 64 * NPAD + HP * NPAD + Dc * NPAD + NPAD
                + 512 * 320 + 320 * 320 + 320 * 128;
        prep_kernel<<<(tot + 255) / 256, 256>>>(gen1_w, gen2_w, head_w, gen2_b,
                                                enc1_w, enc2_w, zm_w, zv_w);
    }

    // fused encoder (one kernel: enc1 -> enc2 -> zm/zv -> z)
    enc_kernel<<<Bc / RPC, 320>>>(x, eps, enc1_b, enc2_b, zm_b, zv_b, zm, zlv, z);

    // fused decoder
    const int smem_bytes = (40960 + 8192 + 8192) * 4;  // 229376 B
    cudaFuncSetAttribute(decoder_kernel, cudaFuncAttributeMaxDynamicSharedMemorySize,
                         smem_bytes);
    decoder_kernel<<<BD / 128, 256, smem_bytes>>>(W, z, head_b, xmean);
}